// round 13
// baseline (speedup 1.0000x reference)
#include <cuda_runtime.h>
#include <cuda_bf16.h>
#include <cuda_fp16.h>
#include <cstdint>

#define BATCH 2
#define SEQ 2048
#define DMODEL 2048
#define NHEAD 16
#define HDIM 128
#define MTOT (BATCH*SEQ)          // 4096
#define NTOK (MTOT*DMODEL)        // 8388608
#define NW   (DMODEL*DMODEL)      // 4194304

// ---------------- scratch (device globals: allocation-free) ----------------
__device__ alignas(16) __half g_x16h[NTOK],  g_x16c[NTOK];
__device__ alignas(16) __half g_wq16h[NW],   g_wq16c[NW];
__device__ alignas(16) __half g_wk16h[NW],   g_wk16c[NW];
__device__ alignas(16) __half g_wv16h[NW],   g_wv16c[NW];
__device__ alignas(16) __half g_wo16h[NW],   g_wo16c[NW];
__device__ alignas(16) __nv_bfloat16 g_q_h[NTOK], g_q_l[NTOK];
__device__ alignas(16) __nv_bfloat16 g_k_h[NTOK], g_k_l[NTOK];
__device__ alignas(16) __nv_bfloat16 g_v_h[NTOK], g_v_l[NTOK];
__device__ alignas(16) __nv_bfloat16 g_vt_h[NTOK], g_vt_l[NTOK];
__device__ alignas(16) __half g_c16h[NTOK], g_c16c[NTOK];

// ---------------- helpers ----------------
__device__ __forceinline__ uint32_t smem_u32(const void* p) {
    uint32_t a;
    asm("{ .reg .u64 t; cvta.to.shared.u64 t, %1; cvt.u32.u64 %0, t; }" : "=r"(a) : "l"(p));
    return a;
}

__device__ __forceinline__ void mma_bf16(float* c, const uint32_t* a, const uint32_t* b)
{
    asm volatile(
        "mma.sync.aligned.m16n8k16.row.col.f32.bf16.bf16.f32 "
        "{%0,%1,%2,%3}, {%4,%5,%6,%7}, {%8,%9}, {%0,%1,%2,%3};\n"
        : "+f"(c[0]), "+f"(c[1]), "+f"(c[2]), "+f"(c[3])
        : "r"(a[0]), "r"(a[1]), "r"(a[2]), "r"(a[3]), "r"(b[0]), "r"(b[1]));
}

__device__ __forceinline__ void mma_f16(float* c, const uint32_t* a, const uint32_t* b)
{
    asm volatile(
        "mma.sync.aligned.m16n8k16.row.col.f32.f16.f16.f32 "
        "{%0,%1,%2,%3}, {%4,%5,%6,%7}, {%8,%9}, {%0,%1,%2,%3};\n"
        : "+f"(c[0]), "+f"(c[1]), "+f"(c[2]), "+f"(c[3])
        : "r"(a[0]), "r"(a[1]), "r"(a[2]), "r"(a[3]), "r"(b[0]), "r"(b[1]));
}

__device__ __forceinline__ void ldsm4(uint32_t& r0, uint32_t& r1, uint32_t& r2, uint32_t& r3,
                                      uint32_t addr)
{
    asm volatile("ldmatrix.sync.aligned.m8n8.x4.shared.b16 {%0,%1,%2,%3}, [%4];"
                 : "=r"(r0), "=r"(r1), "=r"(r2), "=r"(r3) : "r"(addr));
}

// bf16 hi/lo split pack (for Q,K,V and attention internals)
__device__ __forceinline__ uint32_t pack_split(float x, float y, uint32_t& lo_out)
{
    __nv_bfloat16 hx = __float2bfloat16(x);
    __nv_bfloat16 hy = __float2bfloat16(y);
    __nv_bfloat16 lx = __float2bfloat16(x - __bfloat162float(hx));
    __nv_bfloat16 ly = __float2bfloat16(y - __bfloat162float(hy));
    __nv_bfloat162 h2 = __halves2bfloat162(hx, hy);
    __nv_bfloat162 l2 = __halves2bfloat162(lx, ly);
    lo_out = *(uint32_t*)&l2;
    return *(uint32_t*)&h2;
}

// fp16 Karatsuba pair pack: h = fp16(x), c = fp16(h + 64*(x-h))
__device__ __forceinline__ uint32_t pack_f16pair(float x, float y, uint32_t& c_out)
{
    __half hx = __float2half_rn(x);
    __half hy = __float2half_rn(y);
    float fx = __half2float(hx), fy = __half2float(hy);
    __half cx = __float2half_rn(fx + 64.f*(x - fx));
    __half cy = __float2half_rn(fy + 64.f*(y - fy));
    __half2 h2 = __halves2half2(hx, hy);
    __half2 c2 = __halves2half2(cx, cy);
    c_out = *(uint32_t*)&c2;
    return *(uint32_t*)&h2;
}

// cp.async primitives
__device__ __forceinline__ void cp16(uint32_t dst, const void* src) {
    asm volatile("cp.async.cg.shared.global [%0], [%1], 16;" :: "r"(dst), "l"(src));
}
__device__ __forceinline__ void cp_commit() {
    asm volatile("cp.async.commit_group;" ::: "memory");
}
template<int N> __device__ __forceinline__ void cp_wait() {
    asm volatile("cp.async.wait_group %0;" :: "n"(N) : "memory");
}

// ---------------- fp32 -> fp16 Karatsuba pair split ----------------
__global__ void split16_kernel(const float4* __restrict__ src,
                               uint2* __restrict__ h, uint2* __restrict__ c, int n4)
{
    int i = blockIdx.x * blockDim.x + threadIdx.x;
    if (i >= n4) return;
    float4 v = src[i];
    uint32_t c0, c1;
    uint32_t h0 = pack_f16pair(v.x, v.y, c0);
    uint32_t h1 = pack_f16pair(v.z, v.w, c1);
    h[i] = make_uint2(h0, h1);
    c[i] = make_uint2(c0, c1);
}

struct SplitW {
    const float4 *s0, *s1, *s2, *s3;
    uint2 *h0, *h1, *h2, *h3;
    uint2 *c0, *c1, *c2, *c3;
};
__global__ void split16x4_kernel(SplitW w, int n4)
{
    int i = blockIdx.x * blockDim.x + threadIdx.x;
    if (i >= n4) return;
    int z = blockIdx.z;
    const float4* src = (z == 0) ? w.s0 : (z == 1) ? w.s1 : (z == 2) ? w.s2 : w.s3;
    uint2* h = (z == 0) ? w.h0 : (z == 1) ? w.h1 : (z == 2) ? w.h2 : w.h3;
    uint2* c = (z == 0) ? w.c0 : (z == 1) ? w.c1 : (z == 2) ? w.c2 : w.c3;
    float4 v = src[i];
    uint32_t c0, c1;
    uint32_t h0 = pack_f16pair(v.x, v.y, c0);
    uint32_t h1 = pack_f16pair(v.z, v.w, c1);
    h[i] = make_uint2(h0, h1);
    c[i] = make_uint2(c0, c1);
}

// ---------------- per-batch 2048x2048 bf16 transpose (hi+lo fused) ----------
__global__ void transpose_bf16(const __nv_bfloat16* __restrict__ in_h,
                               __nv_bfloat16* __restrict__ out_h,
                               const __nv_bfloat16* __restrict__ in_l,
                               __nv_bfloat16* __restrict__ out_l)
{
    __shared__ __nv_bfloat16 tile[32][33];
    const int bx = blockIdx.x * 32;
    const int by = blockIdx.y * 32;
    const int b  = blockIdx.z & 1;
    const int sel = blockIdx.z >> 1;
    const __nv_bfloat16* in  = sel ? in_l  : in_h;
    __nv_bfloat16*       out = sel ? out_l : out_h;
    const long boff = (long)b * 2048 * 2048;
    const int tx = threadIdx.x & 31;
    const int ty = threadIdx.x >> 5;
#pragma unroll
    for (int j = 0; j < 4; j++) {
        int sl = ty + j*8;
        tile[sl][tx] = in[boff + (long)(by + sl)*2048 + bx + tx];
    }
    __syncthreads();
#pragma unroll
    for (int j = 0; j < 4; j++) {
        int hl = ty + j*8;
        out[boff + (long)(bx + hl)*2048 + by + tx] = tile[tx][hl];
    }
}

// ---------------------------------------------------------------------------
// fp16 Karatsuba 2-pass GEMM: C = A·B^T via acc1 += ah·bh ; acc2 += ac·bc ;
// result = acc1 + (acc2-acc1)/64.
// BM=128, BN=128, BK=32, 512 threads (16 warps, warp tile 32x32),
// 2-stage cp.async, ldmatrix, 2 CTAs/SM. Fused QKV via blockIdx.x>>4.
// ---------------------------------------------------------------------------
#define S_AH 0
#define S_AC 10240
#define S_BH 20480
#define S_BC 30720
#define STG  40960
#define GEMM_SMEM (2*STG)   // 81920 -> 2 CTAs/SM

struct GemmArgs {
    const __half *Ah, *Ac;
    const __half *Bh0, *Bc0, *Bh1, *Bc1, *Bh2, *Bc2;
    float* Cf;
    __nv_bfloat16 *Ch0, *Cl0, *Ch1, *Cl1, *Ch2, *Cl2;
    const float* bias;
};

__device__ __forceinline__ void issue_tile4(uint32_t sb,
    const __half* __restrict__ Ah, const __half* __restrict__ Ac,
    const __half* __restrict__ Bh, const __half* __restrict__ Bc,
    int m0, int n0, int kofs, int tid)
{
    int r = tid >> 2, c = tid & 3;
    uint32_t so = r*80 + c*16;
    long ga = (long)(m0 + r)*DMODEL + kofs + c*8;
    long gb = (long)(n0 + r)*DMODEL + kofs + c*8;
    cp16(sb + S_AH + so, Ah + ga);
    cp16(sb + S_AC + so, Ac + ga);
    cp16(sb + S_BH + so, Bh + gb);
    cp16(sb + S_BC + so, Bc + gb);
}

template<bool SPLIT_OUT>
__global__ __launch_bounds__(512, 2)
void gemm4(GemmArgs a)
{
    extern __shared__ __align__(16) char gsm[];
    const uint32_t smb = smem_u32(gsm);

    const int tid  = threadIdx.x;
    const int lane = tid & 31;
    const int wid  = tid >> 5;       // 0..15
    const int wm   = wid & 3;        // m-quarter (32 rows)
    const int wn   = wid >> 2;       // n-quarter (32 cols)
    const int g    = lane >> 2;
    const int t    = lane & 3;
    const int sub  = lane & 7;
    const int sel  = lane >> 3;

    // ldmatrix per-lane offsets (pitch 80B)
    const uint32_t aoff = ((sel & 1)*8 + sub)*80u + (uint32_t)(sel >> 1)*16u;
    const uint32_t boff = ((sel >> 1)*8 + sub)*80u + (uint32_t)(sel & 1)*16u;

    const int bsel = blockIdx.x >> 4;
    const int n0   = (blockIdx.x & 15) * 128;
    const int m0   = blockIdx.y * 128;

    const __half* Bh = (bsel == 0) ? a.Bh0 : (bsel == 1) ? a.Bh1 : a.Bh2;
    const __half* Bc = (bsel == 0) ? a.Bc0 : (bsel == 1) ? a.Bc1 : a.Bc2;

    float acc1[2][4][4], acc2[2][4][4];
#pragma unroll
    for (int mf = 0; mf < 2; mf++)
#pragma unroll
        for (int nf = 0; nf < 4; nf++)
#pragma unroll
            for (int c = 0; c < 4; c++) { acc1[mf][nf][c] = 0.f; acc2[mf][nf][c] = 0.f; }

    const int nk = DMODEL / 32;   // 64

    issue_tile4(smb,       a.Ah, a.Ac, Bh, Bc, m0, n0, 0,  tid);
    cp_commit();
    issue_tile4(smb + STG, a.Ah, a.Ac, Bh, Bc, m0, n0, 32, tid);
    cp_commit();

    for (int kt = 0; kt < nk; kt++) {
        cp_wait<1>();
        __syncthreads();

        const uint32_t sb32 = smb + (kt & 1)*STG;
        const uint32_t sbAH = sb32 + S_AH + (uint32_t)(wm*32)*80u;
        const uint32_t sbAC = sb32 + S_AC + (uint32_t)(wm*32)*80u;
        const uint32_t sbBH = sb32 + S_BH + (uint32_t)(wn*32)*80u;
        const uint32_t sbBC = sb32 + S_BC + (uint32_t)(wn*32)*80u;

#pragma unroll
        for (int ks = 0; ks < 2; ks++) {
            const uint32_t kb = ks*32;
            // pass 1: hi x hi
            {
                uint32_t ah[2][4], bh[4][2];
#pragma unroll
                for (int mf = 0; mf < 2; mf++)
                    ldsm4(ah[mf][0], ah[mf][1], ah[mf][2], ah[mf][3],
                          sbAH + (uint32_t)(mf*16)*80u + kb + aoff);
#pragma unroll
                for (int p = 0; p < 2; p++)
                    ldsm4(bh[2*p][0], bh[2*p][1], bh[2*p+1][0], bh[2*p+1][1],
                          sbBH + (uint32_t)(p*16)*80u + kb + boff);
#pragma unroll
                for (int mf = 0; mf < 2; mf++)
#pragma unroll
                    for (int nf = 0; nf < 4; nf++)
                        mma_f16(acc1[mf][nf], ah[mf], bh[nf]);
            }
            // pass 2: combined x combined
            {
                uint32_t ac[2][4], bc[4][2];
#pragma unroll
                for (int mf = 0; mf < 2; mf++)
                    ldsm4(ac[mf][0], ac[mf][1], ac[mf][2], ac[mf][3],
                          sbAC + (uint32_t)(mf*16)*80u + kb + aoff);
#pragma unroll
                for (int p = 0; p < 2; p++)
                    ldsm4(bc[2*p][0], bc[2*p][1], bc[2*p+1][0], bc[2*p+1][1],
                          sbBC + (uint32_t)(p*16)*80u + kb + boff);
#pragma unroll
                for (int mf = 0; mf < 2; mf++)
#pragma unroll
                    for (int nf = 0; nf < 4; nf++)
                        mma_f16(acc2[mf][nf], ac[mf], bc[nf]);
            }
        }
        __syncthreads();

        if (kt + 2 < nk)
            issue_tile4(smb + (kt & 1)*STG,
                        a.Ah, a.Ac, Bh, Bc, m0, n0, (kt+2)*32, tid);
        cp_commit();
    }

    __nv_bfloat16* Ch = (bsel == 0) ? a.Ch0 : (bsel == 1) ? a.Ch1 : a.Ch2;
    __nv_bfloat16* Cl = (bsel == 0) ? a.Cl0 : (bsel == 1) ? a.Cl1 : a.Cl2;

    const float KINV = 0.015625f;   // 1/64
#pragma unroll
    for (int nf = 0; nf < 4; nf++) {
        int col = n0 + wn*32 + nf*8 + 2*t;
        float b0 = 0.f, b1 = 0.f;
        if (!SPLIT_OUT && a.bias) { b0 = a.bias[col]; b1 = a.bias[col + 1]; }
#pragma unroll
        for (int mf = 0; mf < 2; mf++) {
            int row = m0 + wm*32 + mf*16 + g;
            float v0 = acc1[mf][nf][0] + (acc2[mf][nf][0] - acc1[mf][nf][0])*KINV;
            float v1 = acc1[mf][nf][1] + (acc2[mf][nf][1] - acc1[mf][nf][1])*KINV;
            float v2 = acc1[mf][nf][2] + (acc2[mf][nf][2] - acc1[mf][nf][2])*KINV;
            float v3 = acc1[mf][nf][3] + (acc2[mf][nf][3] - acc1[mf][nf][3])*KINV;
            if (SPLIT_OUT) {
                uint32_t l0, l1;
                uint32_t h0 = pack_split(v0, v1, l0);
                uint32_t h1 = pack_split(v2, v3, l1);
                *(uint32_t*)(Ch + (long)row*DMODEL + col)     = h0;
                *(uint32_t*)(Cl + (long)row*DMODEL + col)     = l0;
                *(uint32_t*)(Ch + (long)(row+8)*DMODEL + col) = h1;
                *(uint32_t*)(Cl + (long)(row+8)*DMODEL + col) = l1;
            } else {
                *(float2*)(a.Cf + (long)row*DMODEL + col)     = make_float2(v0 + b0, v1 + b1);
                *(float2*)(a.Cf + (long)(row+8)*DMODEL + col) = make_float2(v2 + b0, v3 + b1);
            }
        }
    }
}

// ---------------------------------------------------------------------------
// Tensor-core causal flash attention, bf16x3, ldmatrix (R12 design);
// epilogue now emits fp16 Karatsuba pair for the WO GEMM.
// ---------------------------------------------------------------------------
#define AP 136
#define VP 72
#define ATTN_SMEM ((4*64*AP + 2*128*VP)*2)   // 106496 bytes

__global__ __launch_bounds__(128)
void attn_mma(const __nv_bfloat16* __restrict__ Qh, const __nv_bfloat16* __restrict__ Ql,
              const __nv_bfloat16* __restrict__ Kh, const __nv_bfloat16* __restrict__ Kl,
              const __nv_bfloat16* __restrict__ Vth, const __nv_bfloat16* __restrict__ Vtl,
              __half* __restrict__ Ch, __half* __restrict__ Cc)
{
    extern __shared__ __nv_bfloat16 sm[];
    __nv_bfloat16* sQh = sm;
    __nv_bfloat16* sQl = sQh + 64*AP;
    __nv_bfloat16* sKh = sQl + 64*AP;
    __nv_bfloat16* sKl = sKh + 64*AP;
    __nv_bfloat16* sVh = sKl + 64*AP;
    __nv_bfloat16* sVl = sVh + 128*VP;

    const uint32_t smb   = smem_u32(sm);
    const uint32_t sQh32 = smb;
    const uint32_t sQl32 = smb + 1*64*AP*2;
    const uint32_t sKh32 = smb + 2*64*AP*2;
    const uint32_t sKl32 = smb + 3*64*AP*2;
    const uint32_t sVh32 = smb + 4*64*AP*2;
    const uint32_t sVl32 = sVh32 + 128*VP*2;

    const int tid  = threadIdx.x;
    const int lane = tid & 31;
    const int wid  = tid >> 5;
    const int g    = lane >> 2;
    const int t    = lane & 3;
    const int sub  = lane & 7;
    const int sel  = lane >> 3;

    const uint32_t qoff = ((sel & 1)*8 + sub)*(AP*2u) + (uint32_t)(sel >> 1)*16u;
    const uint32_t koff = ((sel >> 1)*8 + sub)*(AP*2u) + (uint32_t)(sel & 1)*16u;
    const uint32_t voff = ((sel >> 1)*8 + sub)*(VP*2u) + (uint32_t)(sel & 1)*16u;

    const int qt = gridDim.x - 1 - blockIdx.x;   // LPT ordering
    const int h  = blockIdx.y;
    const int b  = blockIdx.z;
    const int q0 = qt * 64;

    const long qbase = ((long)(b*SEQ + q0))*DMODEL + h*HDIM;
#pragma unroll
    for (int i = 0; i < 8; i++) {
        int u = tid + 128*i;
        int r = u >> 4, c = (u & 15)*8;
        *(uint4*)(sQh + r*AP + c) = *(const uint4*)(Qh + qbase + (long)r*DMODEL + c);
        *(uint4*)(sQl + r*AP + c) = *(const uint4*)(Ql + qbase + (long)r*DMODEL + c);
    }

    float accO[16][4];
#pragma unroll
    for (int nb = 0; nb < 16; nb++)
#pragma unroll
        for (int c = 0; c < 4; c++) accO[nb][c] = 0.f;
    float m2[2] = {-1e30f, -1e30f};
    float lsum[2] = {0.f, 0.f};

    const float SC2 = 0.08838834764831845f * 1.4426950408889634f;
    const long vtbase = ((long)((b*NHEAD + h)*HDIM))*SEQ;

    for (int kt = 0; kt <= qt; kt++) {
        const int k0 = kt * 64;
        const long kbase = ((long)(b*SEQ + k0))*DMODEL + h*HDIM;
#pragma unroll
        for (int i = 0; i < 8; i++) {
            int u = tid + 128*i;
            int r = u >> 4, c = (u & 15)*8;
            *(uint4*)(sKh + r*AP + c) = *(const uint4*)(Kh + kbase + (long)r*DMODEL + c);
            *(uint4*)(sKl + r*AP + c) = *(const uint4*)(Kl + kbase + (long)r*DMODEL + c);
        }
#pragma unroll
        for (int i = 0; i < 8; i++) {
            int u = tid + 128*i;
            int d = u >> 3, c = (u & 7)*8;
            *(uint4*)(sVh + d*VP + c) = *(const uint4*)(Vth + vtbase + (long)d*SEQ + k0 + c);
            *(uint4*)(sVl + d*VP + c) = *(const uint4*)(Vtl + vtbase + (long)d*SEQ + k0 + c);
        }
        __syncthreads();

        float s[8][4];
#pragma unroll
        for (int nb = 0; nb < 8; nb++)
#pragma unroll
            for (int c = 0; c < 4; c++) s[nb][c] = 0.f;

        const uint32_t qbaseb = (uint32_t)(wid*16)*(AP*2u);
#pragma unroll
        for (int kc = 0; kc < 8; kc++) {
            const uint32_t kb = kc*32;
            uint32_t ah[4], al[4];
            ldsm4(ah[0], ah[1], ah[2], ah[3], sQh32 + qbaseb + kb + qoff);
            ldsm4(al[0], al[1], al[2], al[3], sQl32 + qbaseb + kb + qoff);
#pragma unroll
            for (int p = 0; p < 4; p++) {
                uint32_t bh[2][2], bl[2][2];
                ldsm4(bh[0][0], bh[0][1], bh[1][0], bh[1][1],
                      sKh32 + (uint32_t)(p*16)*(AP*2u) + kb + koff);
                ldsm4(bl[0][0], bl[0][1], bl[1][0], bl[1][1],
                      sKl32 + (uint32_t)(p*16)*(AP*2u) + kb + koff);
#pragma unroll
                for (int e = 0; e < 2; e++) {
                    mma_bf16(s[2*p + e], ah, bh[e]);
                    mma_bf16(s[2*p + e], ah, bl[e]);
                    mma_bf16(s[2*p + e], al, bh[e]);
                }
            }
        }

        if (kt == qt) {
            const int r0 = wid*16 + g, r1 = r0 + 8;
#pragma unroll
            for (int nb = 0; nb < 8; nb++) {
                int c0 = nb*8 + 2*t, c1 = c0 + 1;
                if (c0 > r0) s[nb][0] = -1e30f;
                if (c1 > r0) s[nb][1] = -1e30f;
                if (c0 > r1) s[nb][2] = -1e30f;
                if (c1 > r1) s[nb][3] = -1e30f;
            }
        }

        float mx0 = -1e30f, mx1 = -1e30f;
#pragma unroll
        for (int nb = 0; nb < 8; nb++) {
            mx0 = fmaxf(mx0, fmaxf(s[nb][0], s[nb][1]));
            mx1 = fmaxf(mx1, fmaxf(s[nb][2], s[nb][3]));
        }
        mx0 *= SC2; mx1 *= SC2;
#pragma unroll
        for (int off = 1; off <= 2; off <<= 1) {
            mx0 = fmaxf(mx0, __shfl_xor_sync(0xffffffffu, mx0, off));
            mx1 = fmaxf(mx1, __shfl_xor_sync(0xffffffffu, mx1, off));
        }
        float mn0 = fmaxf(m2[0], mx0), mn1 = fmaxf(m2[1], mx1);
        float corr0 = exp2f(m2[0] - mn0), corr1 = exp2f(m2[1] - mn1);
        float sum0 = 0.f, sum1 = 0.f;
#pragma unroll
        for (int nb = 0; nb < 8; nb++) {
            s[nb][0] = exp2f(s[nb][0]*SC2 - mn0);
            s[nb][1] = exp2f(s[nb][1]*SC2 - mn0);
            s[nb][2] = exp2f(s[nb][2]*SC2 - mn1);
            s[nb][3] = exp2f(s[nb][3]*SC2 - mn1);
            sum0 += s[nb][0] + s[nb][1];
            sum1 += s[nb][2] + s[nb][3];
        }
#pragma unroll
        for (int off = 1; off <= 2; off <<= 1) {
            sum0 += __shfl_xor_sync(0xffffffffu, sum0, off);
            sum1 += __shfl_xor_sync(0xffffffffu, sum1, off);
        }
        lsum[0] = lsum[0]*corr0 + sum0;
        lsum[1] = lsum[1]*corr1 + sum1;
        m2[0] = mn0; m2[1] = mn1;
#pragma unroll
        for (int nb = 0; nb < 16; nb++) {
            accO[nb][0] *= corr0; accO[nb][1] *= corr0;
            accO[nb][2] *= corr1; accO[nb][3] *= corr1;
        }

        uint32_t pah[4][4], pal[4][4];
#pragma unroll
        for (int kc = 0; kc < 4; kc++) {
            pah[kc][0] = pack_split(s[2*kc][0],   s[2*kc][1],   pal[kc][0]);
            pah[kc][1] = pack_split(s[2*kc][2],   s[2*kc][3],   pal[kc][1]);
            pah[kc][2] = pack_split(s[2*kc+1][0], s[2*kc+1][1], pal[kc][2]);
            pah[kc][3] = pack_split(s[2*kc+1][2], s[2*kc+1][3], pal[kc][3]);
        }

#pragma unroll
        for (int kc = 0; kc < 4; kc++) {
            const uint32_t kb = kc*32;
#pragma unroll
            for (int p = 0; p < 8; p++) {
                uint32_t vh[2][2], vl[2][2];
                ldsm4(vh[0][0], vh[0][1], vh[1][0], vh[1][1],
                      sVh32 + (uint32_t)(p*16)*(VP*2u) + kb + voff);
                ldsm4(vl[0][0], vl[0][1], vl[1][0], vl[1][1],
                      sVl32 + (uint32_t)(p*16)*(VP*2u) + kb + voff);
#pragma unroll
                for (int e = 0; e < 2; e++) {
                    mma_bf16(accO[2*p + e], pah[kc], vh[e]);
                    mma_bf16(accO[2*p + e], pah[kc], vl[e]);
                    mma_bf16(accO[2*p + e], pal[kc], vh[e]);
                }
            }
        }
        __syncthreads();
    }

    // epilogue: normalize; write ctx as fp16 Karatsuba pair
    const float inv0 = 1.f / lsum[0], inv1 = 1.f / lsum[1];
    const long obase = ((long)(b*SEQ + q0 + wid*16))*DMODEL + h*HDIM;
#pragma unroll
    for (int nb = 0; nb < 16; nb++) {
        int col = nb*8 + 2*t;
        uint32_t c0, c1;
        uint32_t h0 = pack_f16pair(accO[nb][0]*inv0, accO[nb][1]*inv0, c0);
        uint32_t h1 = pack_f16pair(accO[nb][2]*inv1, accO[nb][3]*inv1, c1);
        *(uint32_t*)(Ch + obase + (long)g*DMODEL + col)     = h0;
        *(uint32_t*)(Cc + obase + (long)g*DMODEL + col)     = c0;
        *(uint32_t*)(Ch + obase + (long)(g+8)*DMODEL + col) = h1;
        *(uint32_t*)(Cc + obase + (long)(g+8)*DMODEL + col) = c1;
    }
}

// ---------------------------------------------------------------------------
// Host launcher
// ---------------------------------------------------------------------------
extern "C" void kernel_launch(void* const* d_in, const int* in_sizes, int n_in,
                              void* d_out, int out_size)
{
    const float* x  = (const float*)d_in[0];
    const float* wq = (const float*)d_in[1];
    const float* wk = (const float*)d_in[2];
    const float* wv = (const float*)d_in[3];
    const float* wo = (const float*)d_in[4];
    const float* bo = (const float*)d_in[5];
    float* out = (float*)d_out;

    __half *x16h, *x16c, *wq16h, *wq16c, *wk16h, *wk16c, *wv16h, *wv16c, *wo16h, *wo16c;
    __half *c16h, *c16c;
    __nv_bfloat16 *qh, *ql, *kh, *kl, *vh, *vl, *vth, *vtl;
    cudaGetSymbolAddress((void**)&x16h, g_x16h);   cudaGetSymbolAddress((void**)&x16c, g_x16c);
    cudaGetSymbolAddress((void**)&wq16h, g_wq16h); cudaGetSymbolAddress((void**)&wq16c, g_wq16c);
    cudaGetSymbolAddress((void**)&wk16h, g_wk16h); cudaGetSymbolAddress((void**)&wk16c, g_wk16c);
    cudaGetSymbolAddress((void**)&wv16h, g_wv16h); cudaGetSymbolAddress((void**)&wv16c, g_wv16c);
    cudaGetSymbolAddress((void**)&wo16h, g_wo16h); cudaGetSymbolAddress((void**)&wo16c, g_wo16c);
    cudaGetSymbolAddress((void**)&qh, g_q_h);      cudaGetSymbolAddress((void**)&ql, g_q_l);
    cudaGetSymbolAddress((void**)&kh, g_k_h);      cudaGetSymbolAddress((void**)&kl, g_k_l);
    cudaGetSymbolAddress((void**)&vh, g_v_h);      cudaGetSymbolAddress((void**)&vl, g_v_l);
    cudaGetSymbolAddress((void**)&vth, g_vt_h);    cudaGetSymbolAddress((void**)&vtl, g_vt_l);
    cudaGetSymbolAddress((void**)&c16h, g_c16h);   cudaGetSymbolAddress((void**)&c16c, g_c16c);

    static bool configured = false;
    if (!configured) {
        cudaFuncSetAttribute(gemm4<true>,  cudaFuncAttributeMaxDynamicSharedMemorySize, GEMM_SMEM);
        cudaFuncSetAttribute(gemm4<false>, cudaFuncAttributeMaxDynamicSharedMemorySize, GEMM_SMEM);
        cudaFuncSetAttribute(attn_mma, cudaFuncAttributeMaxDynamicSharedMemorySize, ATTN_SMEM);
        configured = true;
    }

    // 1) fp16 Karatsuba splits: x + fused 4-weight
    split16_kernel<<<(NTOK/4 + 255)/256, 256>>>((const float4*)x, (uint2*)x16h, (uint2*)x16c, NTOK/4);
    {
        SplitW w = {};
        w.s0 = (const float4*)wq; w.s1 = (const float4*)wk;
        w.s2 = (const float4*)wv; w.s3 = (const float4*)wo;
        w.h0 = (uint2*)wq16h; w.h1 = (uint2*)wk16h; w.h2 = (uint2*)wv16h; w.h3 = (uint2*)wo16h;
        w.c0 = (uint2*)wq16c; w.c1 = (uint2*)wk16c; w.c2 = (uint2*)wv16c; w.c3 = (uint2*)wo16c;
        split16x4_kernel<<<dim3((NW/4 + 255)/256, 1, 4), 256>>>(w, NW/4);
    }

    // 2) fused QKV projection (fp16 Karatsuba), outputs bf16 hi/lo for attention
    {
        GemmArgs a = {};
        a.Ah = x16h; a.Ac = x16c;
        a.Bh0 = wq16h; a.Bc0 = wq16c; a.Bh1 = wk16h; a.Bc1 = wk16c; a.Bh2 = wv16h; a.Bc2 = wv16c;
        a.Ch0 = qh;  a.Cl0 = ql;  a.Ch1 = kh;  a.Cl1 = kl;  a.Ch2 = vh;  a.Cl2 = vl;
        gemm4<true><<<dim3(48, MTOT/128), 512, GEMM_SMEM>>>(a);
    }

    // 3) V transpose, hi and lo fused
    transpose_bf16<<<dim3(64, 64, 2*BATCH), 256>>>(vh, vth, vl, vtl);

    // 4) attention (bf16x3), emits ctx as fp16 Karatsuba pair
    attn_mma<<<dim3(SEQ/64, NHEAD, BATCH), 128, ATTN_SMEM>>>(qh, ql, kh, kl, vth, vtl, c16h, c16c);

    // 5) output projection (fp16 Karatsuba, fp32 + bias out)
    {
        GemmArgs a = {};
        a.Ah = c16h; a.Ac = c16c;
        a.Bh0 = wo16h; a.Bc0 = wo16c; a.Bh1 = wo16h; a.Bc1 = wo16c; a.Bh2 = wo16h; a.Bc2 = wo16c;
        a.Cf = out; a.bias = bo;
        gemm4<false><<<dim3(16, MTOT/128), 512, GEMM_SMEM>>>(a);
    }
}

// round 15
// speedup vs baseline: 2.3032x; 2.3032x over previous
#include <cuda_runtime.h>
#include <cuda_bf16.h>
#include <cuda_fp16.h>
#include <cstdint>

#define BATCH 2
#define SEQ 2048
#define DMODEL 2048
#define NHEAD 16
#define HDIM 128
#define MTOT (BATCH*SEQ)          // 4096
#define NTOK (MTOT*DMODEL)        // 8388608
#define NW   (DMODEL*DMODEL)      // 4194304

// ---------------- scratch (device globals: allocation-free) ----------------
__device__ alignas(16) __half g_x16h[NTOK],  g_x16c[NTOK];
__device__ alignas(16) __half g_wq16h[NW],   g_wq16c[NW];
__device__ alignas(16) __half g_wk16h[NW],   g_wk16c[NW];
__device__ alignas(16) __half g_wv16h[NW],   g_wv16c[NW];
__device__ alignas(16) __half g_wo16h[NW],   g_wo16c[NW];
__device__ alignas(16) __nv_bfloat16 g_q_h[NTOK], g_q_l[NTOK];
__device__ alignas(16) __nv_bfloat16 g_k_h[NTOK], g_k_l[NTOK];
__device__ alignas(16) __nv_bfloat16 g_v_h[NTOK], g_v_l[NTOK];
__device__ alignas(16) __nv_bfloat16 g_vt_h[NTOK], g_vt_l[NTOK];
__device__ alignas(16) __half g_c16h[NTOK], g_c16c[NTOK];

// ---------------- helpers ----------------
__device__ __forceinline__ uint32_t smem_u32(const void* p) {
    uint32_t a;
    asm("{ .reg .u64 t; cvta.to.shared.u64 t, %1; cvt.u32.u64 %0, t; }" : "=r"(a) : "l"(p));
    return a;
}

__device__ __forceinline__ void mma_bf16(float* c, const uint32_t* a, const uint32_t* b)
{
    asm volatile(
        "mma.sync.aligned.m16n8k16.row.col.f32.bf16.bf16.f32 "
        "{%0,%1,%2,%3}, {%4,%5,%6,%7}, {%8,%9}, {%0,%1,%2,%3};\n"
        : "+f"(c[0]), "+f"(c[1]), "+f"(c[2]), "+f"(c[3])
        : "r"(a[0]), "r"(a[1]), "r"(a[2]), "r"(a[3]), "r"(b[0]), "r"(b[1]));
}

__device__ __forceinline__ void mma_f16(float* c, const uint32_t* a, const uint32_t* b)
{
    asm volatile(
        "mma.sync.aligned.m16n8k16.row.col.f32.f16.f16.f32 "
        "{%0,%1,%2,%3}, {%4,%5,%6,%7}, {%8,%9}, {%0,%1,%2,%3};\n"
        : "+f"(c[0]), "+f"(c[1]), "+f"(c[2]), "+f"(c[3])
        : "r"(a[0]), "r"(a[1]), "r"(a[2]), "r"(a[3]), "r"(b[0]), "r"(b[1]));
}

__device__ __forceinline__ void ldsm4(uint32_t& r0, uint32_t& r1, uint32_t& r2, uint32_t& r3,
                                      uint32_t addr)
{
    asm volatile("ldmatrix.sync.aligned.m8n8.x4.shared.b16 {%0,%1,%2,%3}, [%4];"
                 : "=r"(r0), "=r"(r1), "=r"(r2), "=r"(r3) : "r"(addr));
}

// bf16 hi/lo split pack (attention internals)
__device__ __forceinline__ uint32_t pack_split(float x, float y, uint32_t& lo_out)
{
    __nv_bfloat16 hx = __float2bfloat16(x);
    __nv_bfloat16 hy = __float2bfloat16(y);
    __nv_bfloat16 lx = __float2bfloat16(x - __bfloat162float(hx));
    __nv_bfloat16 ly = __float2bfloat16(y - __bfloat162float(hy));
    __nv_bfloat162 h2 = __halves2bfloat162(hx, hy);
    __nv_bfloat162 l2 = __halves2bfloat162(lx, ly);
    lo_out = *(uint32_t*)&l2;
    return *(uint32_t*)&h2;
}

// fp16 Karatsuba pair pack: h = fp16(x), c = fp16(h + 64*(x-h))
__device__ __forceinline__ uint32_t pack_f16pair(float x, float y, uint32_t& c_out)
{
    __half hx = __float2half_rn(x);
    __half hy = __float2half_rn(y);
    float fx = __half2float(hx), fy = __half2float(hy);
    __half cx = __float2half_rn(fx + 64.f*(x - fx));
    __half cy = __float2half_rn(fy + 64.f*(y - fy));
    __half2 h2 = __halves2half2(hx, hy);
    __half2 c2 = __halves2half2(cx, cy);
    c_out = *(uint32_t*)&c2;
    return *(uint32_t*)&h2;
}

// cp.async primitives
__device__ __forceinline__ void cp16(uint32_t dst, const void* src) {
    asm volatile("cp.async.cg.shared.global [%0], [%1], 16;" :: "r"(dst), "l"(src));
}
__device__ __forceinline__ void cp_commit() {
    asm volatile("cp.async.commit_group;" ::: "memory");
}
template<int N> __device__ __forceinline__ void cp_wait() {
    asm volatile("cp.async.wait_group %0;" :: "n"(N) : "memory");
}

// ---------------- fp32 -> fp16 Karatsuba pair split ----------------
__global__ void split16_kernel(const float4* __restrict__ src,
                               uint2* __restrict__ h, uint2* __restrict__ c, int n4)
{
    int i = blockIdx.x * blockDim.x + threadIdx.x;
    if (i >= n4) return;
    float4 v = src[i];
    uint32_t c0, c1;
    uint32_t h0 = pack_f16pair(v.x, v.y, c0);
    uint32_t h1 = pack_f16pair(v.z, v.w, c1);
    h[i] = make_uint2(h0, h1);
    c[i] = make_uint2(c0, c1);
}

struct SplitW {
    const float4 *s0, *s1, *s2, *s3;
    uint2 *h0, *h1, *h2, *h3;
    uint2 *c0, *c1, *c2, *c3;
};
__global__ void split16x4_kernel(SplitW w, int n4)
{
    int i = blockIdx.x * blockDim.x + threadIdx.x;
    if (i >= n4) return;
    int z = blockIdx.z;
    const float4* src = (z == 0) ? w.s0 : (z == 1) ? w.s1 : (z == 2) ? w.s2 : w.s3;
    uint2* h = (z == 0) ? w.h0 : (z == 1) ? w.h1 : (z == 2) ? w.h2 : w.h3;
    uint2* c = (z == 0) ? w.c0 : (z == 1) ? w.c1 : (z == 2) ? w.c2 : w.c3;
    float4 v = src[i];
    uint32_t c0, c1;
    uint32_t h0 = pack_f16pair(v.x, v.y, c0);
    uint32_t h1 = pack_f16pair(v.z, v.w, c1);
    h[i] = make_uint2(h0, h1);
    c[i] = make_uint2(c0, c1);
}

// ---------------- per-batch 2048x2048 bf16 transpose (hi+lo fused) ----------
__global__ void transpose_bf16(const __nv_bfloat16* __restrict__ in_h,
                               __nv_bfloat16* __restrict__ out_h,
                               const __nv_bfloat16* __restrict__ in_l,
                               __nv_bfloat16* __restrict__ out_l)
{
    __shared__ __nv_bfloat16 tile[32][33];
    const int bx = blockIdx.x * 32;
    const int by = blockIdx.y * 32;
    const int b  = blockIdx.z & 1;
    const int sel = blockIdx.z >> 1;
    const __nv_bfloat16* in  = sel ? in_l  : in_h;
    __nv_bfloat16*       out = sel ? out_l : out_h;
    const long boff = (long)b * 2048 * 2048;
    const int tx = threadIdx.x & 31;
    const int ty = threadIdx.x >> 5;
#pragma unroll
    for (int j = 0; j < 4; j++) {
        int sl = ty + j*8;
        tile[sl][tx] = in[boff + (long)(by + sl)*2048 + bx + tx];
    }
    __syncthreads();
#pragma unroll
    for (int j = 0; j < 4; j++) {
        int hl = ty + j*8;
        out[boff + (long)(bx + hl)*2048 + by + tx] = tile[tx][hl];
    }
}

// ---------------------------------------------------------------------------
// fp16 Karatsuba 2-pass GEMM: acc1 += ah·bh ; acc2 += ac·bc ;
// result = acc1 + (acc2-acc1)/64.
// BM=128, BN=64, BK=32, 256 threads (8 warps, warp tile 32x32),
// 2-stage cp.async, ldmatrix, 2 CTAs/SM (128-reg cap, no spills).
// Fused QKV: B/C selected by blockIdx.x>>5 (32 n-blocks per output).
// ---------------------------------------------------------------------------
#define S_AH 0
#define S_AC 10240
#define S_BH 20480
#define S_BC 25600
#define STG  30720
#define GEMM_SMEM (2*STG)   // 61440 -> 2 CTAs/SM

struct GemmArgs {
    const __half *Ah, *Ac;
    const __half *Bh0, *Bc0, *Bh1, *Bc1, *Bh2, *Bc2;
    float* Cf;
    __nv_bfloat16 *Ch0, *Cl0, *Ch1, *Cl1, *Ch2, *Cl2;
    const float* bias;
};

__device__ __forceinline__ void issue_tile5(uint32_t sb,
    const __half* __restrict__ Ah, const __half* __restrict__ Ac,
    const __half* __restrict__ Bh, const __half* __restrict__ Bc,
    int m0, int n0, int kofs, int tid)
{
#pragma unroll
    for (int i = 0; i < 2; i++) {
        int idx = tid + 256*i;
        int r = idx >> 2, c = idx & 3;
        uint32_t so = r*80 + c*16;
        long ga = (long)(m0 + r)*DMODEL + kofs + c*8;
        cp16(sb + S_AH + so, Ah + ga);
        cp16(sb + S_AC + so, Ac + ga);
    }
    {
        int r = tid >> 2, c = tid & 3;
        uint32_t so = r*80 + c*16;
        long gb = (long)(n0 + r)*DMODEL + kofs + c*8;
        cp16(sb + S_BH + so, Bh + gb);
        cp16(sb + S_BC + so, Bc + gb);
    }
}

template<bool SPLIT_OUT>
__global__ __launch_bounds__(256, 2)
void gemm5(GemmArgs a)
{
    extern __shared__ __align__(16) char gsm[];
    const uint32_t smb = smem_u32(gsm);

    const int tid  = threadIdx.x;
    const int lane = tid & 31;
    const int wid  = tid >> 5;       // 0..7
    const int wm   = wid & 3;        // m-quarter (32 rows)
    const int wn   = wid >> 2;       // n-half (32 cols)
    const int g    = lane >> 2;
    const int t    = lane & 3;
    const int sub  = lane & 7;
    const int sel  = lane >> 3;

    // ldmatrix per-lane offsets (pitch 80B)
    const uint32_t aoff = ((sel & 1)*8 + sub)*80u + (uint32_t)(sel >> 1)*16u;
    const uint32_t boff = ((sel >> 1)*8 + sub)*80u + (uint32_t)(sel & 1)*16u;

    const int bsel = blockIdx.x >> 5;               // 0..2 QKV, 0 WO
    const int n0   = (blockIdx.x & 31) * 64;
    const int m0   = blockIdx.y * 128;

    const __half* Bh = (bsel == 0) ? a.Bh0 : (bsel == 1) ? a.Bh1 : a.Bh2;
    const __half* Bc = (bsel == 0) ? a.Bc0 : (bsel == 1) ? a.Bc1 : a.Bc2;

    float acc1[2][4][4], acc2[2][4][4];
#pragma unroll
    for (int mf = 0; mf < 2; mf++)
#pragma unroll
        for (int nf = 0; nf < 4; nf++)
#pragma unroll
            for (int c = 0; c < 4; c++) { acc1[mf][nf][c] = 0.f; acc2[mf][nf][c] = 0.f; }

    const int nk = DMODEL / 32;   // 64

    issue_tile5(smb,       a.Ah, a.Ac, Bh, Bc, m0, n0, 0,  tid);
    cp_commit();
    issue_tile5(smb + STG, a.Ah, a.Ac, Bh, Bc, m0, n0, 32, tid);
    cp_commit();

    for (int kt = 0; kt < nk; kt++) {
        cp_wait<1>();
        __syncthreads();

        const uint32_t sb32 = smb + (kt & 1)*STG;
        const uint32_t sbAH = sb32 + S_AH + (uint32_t)(wm*32)*80u;
        const uint32_t sbAC = sb32 + S_AC + (uint32_t)(wm*32)*80u;
        const uint32_t sbBH = sb32 + S_BH + (uint32_t)(wn*32)*80u;
        const uint32_t sbBC = sb32 + S_BC + (uint32_t)(wn*32)*80u;

#pragma unroll
        for (int ks = 0; ks < 2; ks++) {
            const uint32_t kb = ks*32;
            // pass 1: hi x hi
            {
                uint32_t ah[2][4], bh[4][2];
#pragma unroll
                for (int mf = 0; mf < 2; mf++)
                    ldsm4(ah[mf][0], ah[mf][1], ah[mf][2], ah[mf][3],
                          sbAH + (uint32_t)(mf*16)*80u + kb + aoff);
#pragma unroll
                for (int p = 0; p < 2; p++)
                    ldsm4(bh[2*p][0], bh[2*p][1], bh[2*p+1][0], bh[2*p+1][1],
                          sbBH + (uint32_t)(p*16)*80u + kb + boff);
#pragma unroll
                for (int mf = 0; mf < 2; mf++)
#pragma unroll
                    for (int nf = 0; nf < 4; nf++)
                        mma_f16(acc1[mf][nf], ah[mf], bh[nf]);
            }
            // pass 2: combined x combined
            {
                uint32_t ac[2][4], bc[4][2];
#pragma unroll
                for (int mf = 0; mf < 2; mf++)
                    ldsm4(ac[mf][0], ac[mf][1], ac[mf][2], ac[mf][3],
                          sbAC + (uint32_t)(mf*16)*80u + kb + aoff);
#pragma unroll
                for (int p = 0; p < 2; p++)
                    ldsm4(bc[2*p][0], bc[2*p][1], bc[2*p+1][0], bc[2*p+1][1],
                          sbBC + (uint32_t)(p*16)*80u + kb + boff);
#pragma unroll
                for (int mf = 0; mf < 2; mf++)
#pragma unroll
                    for (int nf = 0; nf < 4; nf++)
                        mma_f16(acc2[mf][nf], ac[mf], bc[nf]);
            }
        }
        __syncthreads();

        if (kt + 2 < nk)
            issue_tile5(smb + (kt & 1)*STG,
                        a.Ah, a.Ac, Bh, Bc, m0, n0, (kt+2)*32, tid);
        cp_commit();
    }

    __nv_bfloat16* Ch = (bsel == 0) ? a.Ch0 : (bsel == 1) ? a.Ch1 : a.Ch2;
    __nv_bfloat16* Cl = (bsel == 0) ? a.Cl0 : (bsel == 1) ? a.Cl1 : a.Cl2;

    const float KINV = 0.015625f;   // 1/64
#pragma unroll
    for (int nf = 0; nf < 4; nf++) {
        int col = n0 + wn*32 + nf*8 + 2*t;
        float b0 = 0.f, b1 = 0.f;
        if (!SPLIT_OUT && a.bias) { b0 = a.bias[col]; b1 = a.bias[col + 1]; }
#pragma unroll
        for (int mf = 0; mf < 2; mf++) {
            int row = m0 + wm*32 + mf*16 + g;
            float v0 = acc1[mf][nf][0] + (acc2[mf][nf][0] - acc1[mf][nf][0])*KINV;
            float v1 = acc1[mf][nf][1] + (acc2[mf][nf][1] - acc1[mf][nf][1])*KINV;
            float v2 = acc1[mf][nf][2] + (acc2[mf][nf][2] - acc1[mf][nf][2])*KINV;
            float v3 = acc1[mf][nf][3] + (acc2[mf][nf][3] - acc1[mf][nf][3])*KINV;
            if (SPLIT_OUT) {
                uint32_t l0, l1;
                uint32_t h0 = pack_split(v0, v1, l0);
                uint32_t h1 = pack_split(v2, v3, l1);
                *(uint32_t*)(Ch + (long)row*DMODEL + col)     = h0;
                *(uint32_t*)(Cl + (long)row*DMODEL + col)     = l0;
                *(uint32_t*)(Ch + (long)(row+8)*DMODEL + col) = h1;
                *(uint32_t*)(Cl + (long)(row+8)*DMODEL + col) = l1;
            } else {
                *(float2*)(a.Cf + (long)row*DMODEL + col)     = make_float2(v0 + b0, v1 + b1);
                *(float2*)(a.Cf + (long)(row+8)*DMODEL + col) = make_float2(v2 + b0, v3 + b1);
            }
        }
    }
}

// ---------------------------------------------------------------------------
// Tensor-core causal flash attention, bf16x3, ldmatrix; emits fp16 pair ctx.
// ---------------------------------------------------------------------------
#define AP 136
#define VP 72
#define ATTN_SMEM ((4*64*AP + 2*128*VP)*2)   // 106496 bytes

__global__ __launch_bounds__(128)
void attn_mma(const __nv_bfloat16* __restrict__ Qh, const __nv_bfloat16* __restrict__ Ql,
              const __nv_bfloat16* __restrict__ Kh, const __nv_bfloat16* __restrict__ Kl,
              const __nv_bfloat16* __restrict__ Vth, const __nv_bfloat16* __restrict__ Vtl,
              __half* __restrict__ Ch, __half* __restrict__ Cc)
{
    extern __shared__ __nv_bfloat16 sm[];
    __nv_bfloat16* sQh = sm;
    __nv_bfloat16* sQl = sQh + 64*AP;
    __nv_bfloat16* sKh = sQl + 64*AP;
    __nv_bfloat16* sKl = sKh + 64*AP;
    __nv_bfloat16* sVh = sKl + 64*AP;
    __nv_bfloat16* sVl = sVh + 128*VP;

    const uint32_t smb   = smem_u32(sm);
    const uint32_t sQh32 = smb;
    const uint32_t sQl32 = smb + 1*64*AP*2;
    const uint32_t sKh32 = smb + 2*64*AP*2;
    const uint32_t sKl32 = smb + 3*64*AP*2;
    const uint32_t sVh32 = smb + 4*64*AP*2;
    const uint32_t sVl32 = sVh32 + 128*VP*2;

    const int tid  = threadIdx.x;
    const int lane = tid & 31;
    const int wid  = tid >> 5;
    const int g    = lane >> 2;
    const int t    = lane & 3;
    const int sub  = lane & 7;
    const int sel  = lane >> 3;

    const uint32_t qoff = ((sel & 1)*8 + sub)*(AP*2u) + (uint32_t)(sel >> 1)*16u;
    const uint32_t koff = ((sel >> 1)*8 + sub)*(AP*2u) + (uint32_t)(sel & 1)*16u;
    const uint32_t voff = ((sel >> 1)*8 + sub)*(VP*2u) + (uint32_t)(sel & 1)*16u;

    const int qt = gridDim.x - 1 - blockIdx.x;   // LPT ordering
    const int h  = blockIdx.y;
    const int b  = blockIdx.z;
    const int q0 = qt * 64;

    const long qbase = ((long)(b*SEQ + q0))*DMODEL + h*HDIM;
#pragma unroll
    for (int i = 0; i < 8; i++) {
        int u = tid + 128*i;
        int r = u >> 4, c = (u & 15)*8;
        *(uint4*)(sQh + r*AP + c) = *(const uint4*)(Qh + qbase + (long)r*DMODEL + c);
        *(uint4*)(sQl + r*AP + c) = *(const uint4*)(Ql + qbase + (long)r*DMODEL + c);
    }

    float accO[16][4];
#pragma unroll
    for (int nb = 0; nb < 16; nb++)
#pragma unroll
        for (int c = 0; c < 4; c++) accO[nb][c] = 0.f;
    float m2[2] = {-1e30f, -1e30f};
    float lsum[2] = {0.f, 0.f};

    const float SC2 = 0.08838834764831845f * 1.4426950408889634f;
    const long vtbase = ((long)((b*NHEAD + h)*HDIM))*SEQ;

    for (int kt = 0; kt <= qt; kt++) {
        const int k0 = kt * 64;
        const long kbase = ((long)(b*SEQ + k0))*DMODEL + h*HDIM;
#pragma unroll
        for (int i = 0; i < 8; i++) {
            int u = tid + 128*i;
            int r = u >> 4, c = (u & 15)*8;
            *(uint4*)(sKh + r*AP + c) = *(const uint4*)(Kh + kbase + (long)r*DMODEL + c);
            *(uint4*)(sKl + r*AP + c) = *(const uint4*)(Kl + kbase + (long)r*DMODEL + c);
        }
#pragma unroll
        for (int i = 0; i < 8; i++) {
            int u = tid + 128*i;
            int d = u >> 3, c = (u & 7)*8;
            *(uint4*)(sVh + d*VP + c) = *(const uint4*)(Vth + vtbase + (long)d*SEQ + k0 + c);
            *(uint4*)(sVl + d*VP + c) = *(const uint4*)(Vtl + vtbase + (long)d*SEQ + k0 + c);
        }
        __syncthreads();

        float s[8][4];
#pragma unroll
        for (int nb = 0; nb < 8; nb++)
#pragma unroll
            for (int c = 0; c < 4; c++) s[nb][c] = 0.f;

        const uint32_t qbaseb = (uint32_t)(wid*16)*(AP*2u);
#pragma unroll
        for (int kc = 0; kc < 8; kc++) {
            const uint32_t kb = kc*32;
            uint32_t ah[4], al[4];
            ldsm4(ah[0], ah[1], ah[2], ah[3], sQh32 + qbaseb + kb + qoff);
            ldsm4(al[0], al[1], al[2], al[3], sQl32 + qbaseb + kb + qoff);
#pragma unroll
            for (int p = 0; p < 4; p++) {
                uint32_t bh[2][2], bl[2][2];
                ldsm4(bh[0][0], bh[0][1], bh[1][0], bh[1][1],
                      sKh32 + (uint32_t)(p*16)*(AP*2u) + kb + koff);
                ldsm4(bl[0][0], bl[0][1], bl[1][0], bl[1][1],
                      sKl32 + (uint32_t)(p*16)*(AP*2u) + kb + koff);
#pragma unroll
                for (int e = 0; e < 2; e++) {
                    mma_bf16(s[2*p + e], ah, bh[e]);
                    mma_bf16(s[2*p + e], ah, bl[e]);
                    mma_bf16(s[2*p + e], al, bh[e]);
                }
            }
        }

        if (kt == qt) {
            const int r0 = wid*16 + g, r1 = r0 + 8;
#pragma unroll
            for (int nb = 0; nb < 8; nb++) {
                int c0 = nb*8 + 2*t, c1 = c0 + 1;
                if (c0 > r0) s[nb][0] = -1e30f;
                if (c1 > r0) s[nb][1] = -1e30f;
                if (c0 > r1) s[nb][2] = -1e30f;
                if (c1 > r1) s[nb][3] = -1e30f;
            }
        }

        float mx0 = -1e30f, mx1 = -1e30f;
#pragma unroll
        for (int nb = 0; nb < 8; nb++) {
            mx0 = fmaxf(mx0, fmaxf(s[nb][0], s[nb][1]));
            mx1 = fmaxf(mx1, fmaxf(s[nb][2], s[nb][3]));
        }
        mx0 *= SC2; mx1 *= SC2;
#pragma unroll
        for (int off = 1; off <= 2; off <<= 1) {
            mx0 = fmaxf(mx0, __shfl_xor_sync(0xffffffffu, mx0, off));
            mx1 = fmaxf(mx1, __shfl_xor_sync(0xffffffffu, mx1, off));
        }
        float mn0 = fmaxf(m2[0], mx0), mn1 = fmaxf(m2[1], mx1);
        float corr0 = exp2f(m2[0] - mn0), corr1 = exp2f(m2[1] - mn1);
        float sum0 = 0.f, sum1 = 0.f;
#pragma unroll
        for (int nb = 0; nb < 8; nb++) {
            s[nb][0] = exp2f(s[nb][0]*SC2 - mn0);
            s[nb][1] = exp2f(s[nb][1]*SC2 - mn0);
            s[nb][2] = exp2f(s[nb][2]*SC2 - mn1);
            s[nb][3] = exp2f(s[nb][3]*SC2 - mn1);
            sum0 += s[nb][0] + s[nb][1];
            sum1 += s[nb][2] + s[nb][3];
        }
#pragma unroll
        for (int off = 1; off <= 2; off <<= 1) {
            sum0 += __shfl_xor_sync(0xffffffffu, sum0, off);
            sum1 += __shfl_xor_sync(0xffffffffu, sum1, off);
        }
        lsum[0] = lsum[0]*corr0 + sum0;
        lsum[1] = lsum[1]*corr1 + sum1;
        m2[0] = mn0; m2[1] = mn1;
#pragma unroll
        for (int nb = 0; nb < 16; nb++) {
            accO[nb][0] *= corr0; accO[nb][1] *= corr0;
            accO[nb][2] *= corr1; accO[nb][3] *= corr1;
        }

        uint32_t pah[4][4], pal[4][4];
#pragma unroll
        for (int kc = 0; kc < 4; kc++) {
            pah[kc][0] = pack_split(s[2*kc][0],   s[2*kc][1],   pal[kc][0]);
            pah[kc][1] = pack_split(s[2*kc][2],   s[2*kc][3],   pal[kc][1]);
            pah[kc][2] = pack_split(s[2*kc+1][0], s[2*kc+1][1], pal[kc][2]);
            pah[kc][3] = pack_split(s[2*kc+1][2], s[2*kc+1][3], pal[kc][3]);
        }

#pragma unroll
        for (int kc = 0; kc < 4; kc++) {
            const uint32_t kb = kc*32;
#pragma unroll
            for (int p = 0; p < 8; p++) {
                uint32_t vh[2][2], vl[2][2];
                ldsm4(vh[0][0], vh[0][1], vh[1][0], vh[1][1],
                      sVh32 + (uint32_t)(p*16)*(VP*2u) + kb + voff);
                ldsm4(vl[0][0], vl[0][1], vl[1][0], vl[1][1],
                      sVl32 + (uint32_t)(p*16)*(VP*2u) + kb + voff);
#pragma unroll
                for (int e = 0; e < 2; e++) {
                    mma_bf16(accO[2*p + e], pah[kc], vh[e]);
                    mma_bf16(accO[2*p + e], pah[kc], vl[e]);
                    mma_bf16(accO[2*p + e], pal[kc], vh[e]);
                }
            }
        }
        __syncthreads();
    }

    const float inv0 = 1.f / lsum[0], inv1 = 1.f / lsum[1];
    const long obase = ((long)(b*SEQ + q0 + wid*16))*DMODEL + h*HDIM;
#pragma unroll
    for (int nb = 0; nb < 16; nb++) {
        int col = nb*8 + 2*t;
        uint32_t c0, c1;
        uint32_t h0 = pack_f16pair(accO[nb][0]*inv0, accO[nb][1]*inv0, c0);
        uint32_t h1 = pack_f16pair(accO[nb][2]*inv1, accO[nb][3]*inv1, c1);
        *(uint32_t*)(Ch + obase + (long)g*DMODEL + col)     = h0;
        *(uint32_t*)(Cc + obase + (long)g*DMODEL + col)     = c0;
        *(uint32_t*)(Ch + obase + (long)(g+8)*DMODEL + col) = h1;
        *(uint32_t*)(Cc + obase + (long)(g+8)*DMODEL + col) = c1;
    }
}

// ---------------------------------------------------------------------------
// Host launcher
// ---------------------------------------------------------------------------
extern "C" void kernel_launch(void* const* d_in, const int* in_sizes, int n_in,
                              void* d_out, int out_size)
{
    const float* x  = (const float*)d_in[0];
    const float* wq = (const float*)d_in[1];
    const float* wk = (const float*)d_in[2];
    const float* wv = (const float*)d_in[3];
    const float* wo = (const float*)d_in[4];
    const float* bo = (const float*)d_in[5];
    float* out = (float*)d_out;

    __half *x16h, *x16c, *wq16h, *wq16c, *wk16h, *wk16c, *wv16h, *wv16c, *wo16h, *wo16c;
    __half *c16h, *c16c;
    __nv_bfloat16 *qh, *ql, *kh, *kl, *vh, *vl, *vth, *vtl;
    cudaGetSymbolAddress((void**)&x16h, g_x16h);   cudaGetSymbolAddress((void**)&x16c, g_x16c);
    cudaGetSymbolAddress((void**)&wq16h, g_wq16h); cudaGetSymbolAddress((void**)&wq16c, g_wq16c);
    cudaGetSymbolAddress((void**)&wk16h, g_wk16h); cudaGetSymbolAddress((void**)&wk16c, g_wk16c);
    cudaGetSymbolAddress((void**)&wv16h, g_wv16h); cudaGetSymbolAddress((void**)&wv16c, g_wv16c);
    cudaGetSymbolAddress((void**)&wo16h, g_wo16h); cudaGetSymbolAddress((void**)&wo16c, g_wo16c);
    cudaGetSymbolAddress((void**)&qh, g_q_h);      cudaGetSymbolAddress((void**)&ql, g_q_l);
    cudaGetSymbolAddress((void**)&kh, g_k_h);      cudaGetSymbolAddress((void**)&kl, g_k_l);
    cudaGetSymbolAddress((void**)&vh, g_v_h);      cudaGetSymbolAddress((void**)&vl, g_v_l);
    cudaGetSymbolAddress((void**)&vth, g_vt_h);    cudaGetSymbolAddress((void**)&vtl, g_vt_l);
    cudaGetSymbolAddress((void**)&c16h, g_c16h);   cudaGetSymbolAddress((void**)&c16c, g_c16c);

    static bool configured = false;
    if (!configured) {
        cudaFuncSetAttribute(gemm5<true>,  cudaFuncAttributeMaxDynamicSharedMemorySize, GEMM_SMEM);
        cudaFuncSetAttribute(gemm5<false>, cudaFuncAttributeMaxDynamicSharedMemorySize, GEMM_SMEM);
        cudaFuncSetAttribute(attn_mma, cudaFuncAttributeMaxDynamicSharedMemorySize, ATTN_SMEM);
        configured = true;
    }

    // 1) fp16 Karatsuba splits: x + fused 4-weight
    split16_kernel<<<(NTOK/4 + 255)/256, 256>>>((const float4*)x, (uint2*)x16h, (uint2*)x16c, NTOK/4);
    {
        SplitW w = {};
        w.s0 = (const float4*)wq; w.s1 = (const float4*)wk;
        w.s2 = (const float4*)wv; w.s3 = (const float4*)wo;
        w.h0 = (uint2*)wq16h; w.h1 = (uint2*)wk16h; w.h2 = (uint2*)wv16h; w.h3 = (uint2*)wo16h;
        w.c0 = (uint2*)wq16c; w.c1 = (uint2*)wk16c; w.c2 = (uint2*)wv16c; w.c3 = (uint2*)wo16c;
        split16x4_kernel<<<dim3((NW/4 + 255)/256, 1, 4), 256>>>(w, NW/4);
    }

    // 2) fused QKV projection (fp16 Karatsuba), outputs bf16 hi/lo for attention
    {
        GemmArgs a = {};
        a.Ah = x16h; a.Ac = x16c;
        a.Bh0 = wq16h; a.Bc0 = wq16c; a.Bh1 = wk16h; a.Bc1 = wk16c; a.Bh2 = wv16h; a.Bc2 = wv16c;
        a.Ch0 = qh;  a.Cl0 = ql;  a.Ch1 = kh;  a.Cl1 = kl;  a.Ch2 = vh;  a.Cl2 = vl;
        gemm5<true><<<dim3(96, MTOT/128), 256, GEMM_SMEM>>>(a);
    }

    // 3) V transpose, hi and lo fused
    transpose_bf16<<<dim3(64, 64, 2*BATCH), 256>>>(vh, vth, vl, vtl);

    // 4) attention (bf16x3), emits ctx as fp16 Karatsuba pair
    attn_mma<<<dim3(SEQ/64, NHEAD, BATCH), 128, ATTN_SMEM>>>(qh, ql, kh, kl, vth, vtl, c16h, c16c);

    // 5) output projection (fp16 Karatsuba, fp32 + bias out)
    {
        GemmArgs a = {};
        a.Ah = c16h; a.Ac = c16c;
        a.Bh0 = wo16h; a.Bc0 = wo16c; a.Bh1 = wo16h; a.Bc1 = wo16c; a.Bh2 = wo16h; a.Bc2 = wo16c;
        a.Cf = out; a.bias = bo;
        gemm5<false><<<dim3(32, MTOT/128), 256, GEMM_SMEM>>>(a);
    }
}

// round 17
// speedup vs baseline: 2.4749x; 1.0746x over previous
#include <cuda_runtime.h>
#include <cuda_bf16.h>
#include <cuda_fp16.h>
#include <cstdint>

#define BATCH 2
#define SEQ 2048
#define DMODEL 2048
#define NHEAD 16
#define HDIM 128
#define MTOT (BATCH*SEQ)          // 4096
#define NTOK (MTOT*DMODEL)        // 8388608
#define NW   (DMODEL*DMODEL)      // 4194304

// ---------------- scratch (device globals: allocation-free) ----------------
__device__ alignas(16) __half g_x16h[NTOK],  g_x16c[NTOK];
__device__ alignas(16) __half g_wq16h[NW],   g_wq16c[NW];
__device__ alignas(16) __half g_wk16h[NW],   g_wk16c[NW];
__device__ alignas(16) __half g_wv16h[NW],   g_wv16c[NW];
__device__ alignas(16) __half g_wo16h[NW],   g_wo16c[NW];
__device__ alignas(16) __nv_bfloat16 g_q_h[NTOK], g_q_l[NTOK];
__device__ alignas(16) __nv_bfloat16 g_k_h[NTOK], g_k_l[NTOK];
__device__ alignas(16) __nv_bfloat16 g_v_h[NTOK], g_v_l[NTOK];
__device__ alignas(16) __nv_bfloat16 g_vt_h[NTOK], g_vt_l[NTOK];
__device__ alignas(16) __half g_c16h[NTOK], g_c16c[NTOK];

// ---------------- helpers ----------------
__device__ __forceinline__ uint32_t smem_u32(const void* p) {
    uint32_t a;
    asm("{ .reg .u64 t; cvta.to.shared.u64 t, %1; cvt.u32.u64 %0, t; }" : "=r"(a) : "l"(p));
    return a;
}

__device__ __forceinline__ void mma_bf16(float* c, const uint32_t* a, const uint32_t* b)
{
    asm volatile(
        "mma.sync.aligned.m16n8k16.row.col.f32.bf16.bf16.f32 "
        "{%0,%1,%2,%3}, {%4,%5,%6,%7}, {%8,%9}, {%0,%1,%2,%3};\n"
        : "+f"(c[0]), "+f"(c[1]), "+f"(c[2]), "+f"(c[3])
        : "r"(a[0]), "r"(a[1]), "r"(a[2]), "r"(a[3]), "r"(b[0]), "r"(b[1]));
}

__device__ __forceinline__ void mma_f16(float* c, const uint32_t* a, const uint32_t* b)
{
    asm volatile(
        "mma.sync.aligned.m16n8k16.row.col.f32.f16.f16.f32 "
        "{%0,%1,%2,%3}, {%4,%5,%6,%7}, {%8,%9}, {%0,%1,%2,%3};\n"
        : "+f"(c[0]), "+f"(c[1]), "+f"(c[2]), "+f"(c[3])
        : "r"(a[0]), "r"(a[1]), "r"(a[2]), "r"(a[3]), "r"(b[0]), "r"(b[1]));
}

__device__ __forceinline__ void ldsm4(uint32_t& r0, uint32_t& r1, uint32_t& r2, uint32_t& r3,
                                      uint32_t addr)
{
    asm volatile("ldmatrix.sync.aligned.m8n8.x4.shared.b16 {%0,%1,%2,%3}, [%4];"
                 : "=r"(r0), "=r"(r1), "=r"(r2), "=r"(r3) : "r"(addr));
}

// bf16 hi/lo split pack (attention internals)
__device__ __forceinline__ uint32_t pack_split(float x, float y, uint32_t& lo_out)
{
    __nv_bfloat16 hx = __float2bfloat16(x);
    __nv_bfloat16 hy = __float2bfloat16(y);
    __nv_bfloat16 lx = __float2bfloat16(x - __bfloat162float(hx));
    __nv_bfloat16 ly = __float2bfloat16(y - __bfloat162float(hy));
    __nv_bfloat162 h2 = __halves2bfloat162(hx, hy);
    __nv_bfloat162 l2 = __halves2bfloat162(lx, ly);
    lo_out = *(uint32_t*)&l2;
    return *(uint32_t*)&h2;
}

// fp16 Karatsuba pair pack: h = fp16(x), c = fp16(h + 64*(x-h))
__device__ __forceinline__ uint32_t pack_f16pair(float x, float y, uint32_t& c_out)
{
    __half hx = __float2half_rn(x);
    __half hy = __float2half_rn(y);
    float fx = __half2float(hx), fy = __half2float(hy);
    __half cx = __float2half_rn(fx + 64.f*(x - fx));
    __half cy = __float2half_rn(fy + 64.f*(y - fy));
    __half2 h2 = __halves2half2(hx, hy);
    __half2 c2 = __halves2half2(cx, cy);
    c_out = *(uint32_t*)&c2;
    return *(uint32_t*)&h2;
}

// cp.async primitives
__device__ __forceinline__ void cp16(uint32_t dst, const void* src) {
    asm volatile("cp.async.cg.shared.global [%0], [%1], 16;" :: "r"(dst), "l"(src));
}
__device__ __forceinline__ void cp_commit() {
    asm volatile("cp.async.commit_group;" ::: "memory");
}
template<int N> __device__ __forceinline__ void cp_wait() {
    asm volatile("cp.async.wait_group %0;" :: "n"(N) : "memory");
}

// ---------------- fp32 -> fp16 Karatsuba pair split ----------------
__global__ void split16_kernel(const float4* __restrict__ src,
                               uint2* __restrict__ h, uint2* __restrict__ c, int n4)
{
    int i = blockIdx.x * blockDim.x + threadIdx.x;
    if (i >= n4) return;
    float4 v = src[i];
    uint32_t c0, c1;
    uint32_t h0 = pack_f16pair(v.x, v.y, c0);
    uint32_t h1 = pack_f16pair(v.z, v.w, c1);
    h[i] = make_uint2(h0, h1);
    c[i] = make_uint2(c0, c1);
}

struct SplitW {
    const float4 *s0, *s1, *s2, *s3;
    uint2 *h0, *h1, *h2, *h3;
    uint2 *c0, *c1, *c2, *c3;
};
__global__ void split16x4_kernel(SplitW w, int n4)
{
    int i = blockIdx.x * blockDim.x + threadIdx.x;
    if (i >= n4) return;
    int z = blockIdx.z;
    const float4* src = (z == 0) ? w.s0 : (z == 1) ? w.s1 : (z == 2) ? w.s2 : w.s3;
    uint2* h = (z == 0) ? w.h0 : (z == 1) ? w.h1 : (z == 2) ? w.h2 : w.h3;
    uint2* c = (z == 0) ? w.c0 : (z == 1) ? w.c1 : (z == 2) ? w.c2 : w.c3;
    float4 v = src[i];
    uint32_t c0, c1;
    uint32_t h0 = pack_f16pair(v.x, v.y, c0);
    uint32_t h1 = pack_f16pair(v.z, v.w, c1);
    h[i] = make_uint2(h0, h1);
    c[i] = make_uint2(c0, c1);
}

// ---------------- per-batch 2048x2048 bf16 transpose (hi+lo fused) ----------
__global__ void transpose_bf16(const __nv_bfloat16* __restrict__ in_h,
                               __nv_bfloat16* __restrict__ out_h,
                               const __nv_bfloat16* __restrict__ in_l,
                               __nv_bfloat16* __restrict__ out_l)
{
    __shared__ __nv_bfloat16 tile[32][33];
    const int bx = blockIdx.x * 32;
    const int by = blockIdx.y * 32;
    const int b  = blockIdx.z & 1;
    const int sel = blockIdx.z >> 1;
    const __nv_bfloat16* in  = sel ? in_l  : in_h;
    __nv_bfloat16*       out = sel ? out_l : out_h;
    const long boff = (long)b * 2048 * 2048;
    const int tx = threadIdx.x & 31;
    const int ty = threadIdx.x >> 5;
#pragma unroll
    for (int j = 0; j < 4; j++) {
        int sl = ty + j*8;
        tile[sl][tx] = in[boff + (long)(by + sl)*2048 + bx + tx];
    }
    __syncthreads();
#pragma unroll
    for (int j = 0; j < 4; j++) {
        int hl = ty + j*8;
        out[boff + (long)(bx + hl)*2048 + by + tx] = tile[tx][hl];
    }
}

// ---------------------------------------------------------------------------
// fp16 Karatsuba 2-pass GEMM: acc1 += ah·bh ; acc2 += ac·bc ;
// result = acc1 + (acc2-acc1)/64.
// BM=128, BN=128, BK=32, 512 threads (16 warps, warp tile 32x32),
// 3-stage cp.async (1 sync per k-tile), ldmatrix, 1 CTA/SM (128-reg cap).
// Grid: x = m-block (fast, L2 reuse of B), y = n-block (+output select).
// ---------------------------------------------------------------------------
#define S_AH 0
#define S_AC 10240
#define S_BH 20480
#define S_BC 30720
#define STG  40960
#define NST  3
#define GEMM_SMEM (NST*STG)   // 122880 -> 1 CTA/SM

struct GemmArgs {
    const __half *Ah, *Ac;
    const __half *Bh0, *Bc0, *Bh1, *Bc1, *Bh2, *Bc2;
    float* Cf;
    __nv_bfloat16 *Ch0, *Cl0, *Ch1, *Cl1, *Ch2, *Cl2;
    const float* bias;
};

__device__ __forceinline__ void issue_tile6(uint32_t sb,
    const __half* __restrict__ Ah, const __half* __restrict__ Ac,
    const __half* __restrict__ Bh, const __half* __restrict__ Bc,
    int m0, int n0, int kofs, int tid)
{
    int r = tid >> 2, c = tid & 3;
    uint32_t so = r*80 + c*16;
    long ga = (long)(m0 + r)*DMODEL + kofs + c*8;
    long gb = (long)(n0 + r)*DMODEL + kofs + c*8;
    cp16(sb + S_AH + so, Ah + ga);
    cp16(sb + S_AC + so, Ac + ga);
    cp16(sb + S_BH + so, Bh + gb);
    cp16(sb + S_BC + so, Bc + gb);
}

template<bool SPLIT_OUT>
__global__ __launch_bounds__(512, 1)
void gemm6(GemmArgs a)
{
    extern __shared__ __align__(16) char gsm[];
    const uint32_t smb = smem_u32(gsm);

    const int tid  = threadIdx.x;
    const int lane = tid & 31;
    const int wid  = tid >> 5;       // 0..15
    const int wm   = wid & 3;        // m-quarter (32 rows)
    const int wn   = wid >> 2;       // n-quarter (32 cols)
    const int g    = lane >> 2;
    const int t    = lane & 3;
    const int sub  = lane & 7;
    const int sel  = lane >> 3;

    // ldmatrix per-lane offsets (pitch 80B)
    const uint32_t aoff = ((sel & 1)*8 + sub)*80u + (uint32_t)(sel >> 1)*16u;
    const uint32_t boff = ((sel >> 1)*8 + sub)*80u + (uint32_t)(sel & 1)*16u;

    const int m0   = blockIdx.x * 128;              // m fast
    const int bsel = blockIdx.y >> 4;               // 0..2 QKV, 0 WO
    const int n0   = (blockIdx.y & 15) * 128;

    const __half* Bh = (bsel == 0) ? a.Bh0 : (bsel == 1) ? a.Bh1 : a.Bh2;
    const __half* Bc = (bsel == 0) ? a.Bc0 : (bsel == 1) ? a.Bc1 : a.Bc2;

    float acc1[2][4][4], acc2[2][4][4];
#pragma unroll
    for (int mf = 0; mf < 2; mf++)
#pragma unroll
        for (int nf = 0; nf < 4; nf++)
#pragma unroll
            for (int c = 0; c < 4; c++) { acc1[mf][nf][c] = 0.f; acc2[mf][nf][c] = 0.f; }

    const int nk = DMODEL / 32;   // 64

    issue_tile6(smb,         a.Ah, a.Ac, Bh, Bc, m0, n0, 0,  tid);
    cp_commit();
    issue_tile6(smb + STG,   a.Ah, a.Ac, Bh, Bc, m0, n0, 32, tid);
    cp_commit();

    for (int kt = 0; kt < nk; kt++) {
        cp_wait<1>();
        __syncthreads();   // group kt landed; all warps done with buffer (kt+2)%3

        if (kt + 2 < nk)
            issue_tile6(smb + ((kt+2)%NST)*STG,
                        a.Ah, a.Ac, Bh, Bc, m0, n0, (kt+2)*32, tid);
        cp_commit();

        const uint32_t sb32 = smb + (kt % NST)*STG;
        const uint32_t sbAH = sb32 + S_AH + (uint32_t)(wm*32)*80u;
        const uint32_t sbAC = sb32 + S_AC + (uint32_t)(wm*32)*80u;
        const uint32_t sbBH = sb32 + S_BH + (uint32_t)(wn*32)*80u;
        const uint32_t sbBC = sb32 + S_BC + (uint32_t)(wn*32)*80u;

#pragma unroll
        for (int ks = 0; ks < 2; ks++) {
            const uint32_t kb = ks*32;
            // pass 1: hi x hi
            {
                uint32_t ah[2][4], bh[4][2];
#pragma unroll
                for (int mf = 0; mf < 2; mf++)
                    ldsm4(ah[mf][0], ah[mf][1], ah[mf][2], ah[mf][3],
                          sbAH + (uint32_t)(mf*16)*80u + kb + aoff);
#pragma unroll
                for (int p = 0; p < 2; p++)
                    ldsm4(bh[2*p][0], bh[2*p][1], bh[2*p+1][0], bh[2*p+1][1],
                          sbBH + (uint32_t)(p*16)*80u + kb + boff);
#pragma unroll
                for (int mf = 0; mf < 2; mf++)
#pragma unroll
                    for (int nf = 0; nf < 4; nf++)
                        mma_f16(acc1[mf][nf], ah[mf], bh[nf]);
            }
            // pass 2: combined x combined
            {
                uint32_t ac[2][4], bc[4][2];
#pragma unroll
                for (int mf = 0; mf < 2; mf++)
                    ldsm4(ac[mf][0], ac[mf][1], ac[mf][2], ac[mf][3],
                          sbAC + (uint32_t)(mf*16)*80u + kb + aoff);
#pragma unroll
                for (int p = 0; p < 2; p++)
                    ldsm4(bc[2*p][0], bc[2*p][1], bc[2*p+1][0], bc[2*p+1][1],
                          sbBC + (uint32_t)(p*16)*80u + kb + boff);
#pragma unroll
                for (int mf = 0; mf < 2; mf++)
#pragma unroll
                    for (int nf = 0; nf < 4; nf++)
                        mma_f16(acc2[mf][nf], ac[mf], bc[nf]);
            }
        }
    }

    __nv_bfloat16* Ch = (bsel == 0) ? a.Ch0 : (bsel == 1) ? a.Ch1 : a.Ch2;
    __nv_bfloat16* Cl = (bsel == 0) ? a.Cl0 : (bsel == 1) ? a.Cl1 : a.Cl2;

    const float KINV = 0.015625f;   // 1/64
#pragma unroll
    for (int nf = 0; nf < 4; nf++) {
        int col = n0 + wn*32 + nf*8 + 2*t;
        float b0 = 0.f, b1 = 0.f;
        if (!SPLIT_OUT && a.bias) { b0 = a.bias[col]; b1 = a.bias[col + 1]; }
#pragma unroll
        for (int mf = 0; mf < 2; mf++) {
            int row = m0 + wm*32 + mf*16 + g;
            float v0 = acc1[mf][nf][0] + (acc2[mf][nf][0] - acc1[mf][nf][0])*KINV;
            float v1 = acc1[mf][nf][1] + (acc2[mf][nf][1] - acc1[mf][nf][1])*KINV;
            float v2 = acc1[mf][nf][2] + (acc2[mf][nf][2] - acc1[mf][nf][2])*KINV;
            float v3 = acc1[mf][nf][3] + (acc2[mf][nf][3] - acc1[mf][nf][3])*KINV;
            if (SPLIT_OUT) {
                uint32_t l0, l1;
                uint32_t h0 = pack_split(v0, v1, l0);
                uint32_t h1 = pack_split(v2, v3, l1);
                *(uint32_t*)(Ch + (long)row*DMODEL + col)     = h0;
                *(uint32_t*)(Cl + (long)row*DMODEL + col)     = l0;
                *(uint32_t*)(Ch + (long)(row+8)*DMODEL + col) = h1;
                *(uint32_t*)(Cl + (long)(row+8)*DMODEL + col) = l1;
            } else {
                *(float2*)(a.Cf + (long)row*DMODEL + col)     = make_float2(v0 + b0, v1 + b1);
                *(float2*)(a.Cf + (long)(row+8)*DMODEL + col) = make_float2(v2 + b0, v3 + b1);
            }
        }
    }
}

// ---------------------------------------------------------------------------
// Tensor-core causal flash attention, bf16x3, ldmatrix; emits fp16 pair ctx.
// ---------------------------------------------------------------------------
#define AP 136
#define VP 72
#define ATTN_SMEM ((4*64*AP + 2*128*VP)*2)   // 106496 bytes

__global__ __launch_bounds__(128)
void attn_mma(const __nv_bfloat16* __restrict__ Qh, const __nv_bfloat16* __restrict__ Ql,
              const __nv_bfloat16* __restrict__ Kh, const __nv_bfloat16* __restrict__ Kl,
              const __nv_bfloat16* __restrict__ Vth, const __nv_bfloat16* __restrict__ Vtl,
              __half* __restrict__ Ch, __half* __restrict__ Cc)
{
    extern __shared__ __nv_bfloat16 sm[];
    __nv_bfloat16* sQh = sm;
    __nv_bfloat16* sQl = sQh + 64*AP;
    __nv_bfloat16* sKh = sQl + 64*AP;
    __nv_bfloat16* sKl = sKh + 64*AP;
    __nv_bfloat16* sVh = sKl + 64*AP;
    __nv_bfloat16* sVl = sVh + 128*VP;

    const uint32_t smb   = smem_u32(sm);
    const uint32_t sQh32 = smb;
    const uint32_t sQl32 = smb + 1*64*AP*2;
    const uint32_t sKh32 = smb + 2*64*AP*2;
    const uint32_t sKl32 = smb + 3*64*AP*2;
    const uint32_t sVh32 = smb + 4*64*AP*2;
    const uint32_t sVl32 = sVh32 + 128*VP*2;

    const int tid  = threadIdx.x;
    const int lane = tid & 31;
    const int wid  = tid >> 5;
    const int g    = lane >> 2;
    const int t    = lane & 3;
    const int sub  = lane & 7;
    const int sel  = lane >> 3;

    const uint32_t qoff = ((sel & 1)*8 + sub)*(AP*2u) + (uint32_t)(sel >> 1)*16u;
    const uint32_t koff = ((sel >> 1)*8 + sub)*(AP*2u) + (uint32_t)(sel & 1)*16u;
    const uint32_t voff = ((sel >> 1)*8 + sub)*(VP*2u) + (uint32_t)(sel & 1)*16u;

    const int qt = gridDim.x - 1 - blockIdx.x;   // LPT ordering
    const int h  = blockIdx.y;
    const int b  = blockIdx.z;
    const int q0 = qt * 64;

    const long qbase = ((long)(b*SEQ + q0))*DMODEL + h*HDIM;
#pragma unroll
    for (int i = 0; i < 8; i++) {
        int u = tid + 128*i;
        int r = u >> 4, c = (u & 15)*8;
        *(uint4*)(sQh + r*AP + c) = *(const uint4*)(Qh + qbase + (long)r*DMODEL + c);
        *(uint4*)(sQl + r*AP + c) = *(const uint4*)(Ql + qbase + (long)r*DMODEL + c);
    }

    float accO[16][4];
#pragma unroll
    for (int nb = 0; nb < 16; nb++)
#pragma unroll
        for (int c = 0; c < 4; c++) accO[nb][c] = 0.f;
    float m2[2] = {-1e30f, -1e30f};
    float lsum[2] = {0.f, 0.f};

    const float SC2 = 0.08838834764831845f * 1.4426950408889634f;
    const long vtbase = ((long)((b*NHEAD + h)*HDIM))*SEQ;

    for (int kt = 0; kt <= qt; kt++) {
        const int k0 = kt * 64;
        const long kbase = ((long)(b*SEQ + k0))*DMODEL + h*HDIM;
#pragma unroll
        for (int i = 0; i < 8; i++) {
            int u = tid + 128*i;
            int r = u >> 4, c = (u & 15)*8;
            *(uint4*)(sKh + r*AP + c) = *(const uint4*)(Kh + kbase + (long)r*DMODEL + c);
            *(uint4*)(sKl + r*AP + c) = *(const uint4*)(Kl + kbase + (long)r*DMODEL + c);
        }
#pragma unroll
        for (int i = 0; i < 8; i++) {
            int u = tid + 128*i;
            int d = u >> 3, c = (u & 7)*8;
            *(uint4*)(sVh + d*VP + c) = *(const uint4*)(Vth + vtbase + (long)d*SEQ + k0 + c);
            *(uint4*)(sVl + d*VP + c) = *(const uint4*)(Vtl + vtbase + (long)d*SEQ + k0 + c);
        }
        __syncthreads();

        float s[8][4];
#pragma unroll
        for (int nb = 0; nb < 8; nb++)
#pragma unroll
            for (int c = 0; c < 4; c++) s[nb][c] = 0.f;

        const uint32_t qbaseb = (uint32_t)(wid*16)*(AP*2u);
#pragma unroll
        for (int kc = 0; kc < 8; kc++) {
            const uint32_t kb = kc*32;
            uint32_t ah[4], al[4];
            ldsm4(ah[0], ah[1], ah[2], ah[3], sQh32 + qbaseb + kb + qoff);
            ldsm4(al[0], al[1], al[2], al[3], sQl32 + qbaseb + kb + qoff);
#pragma unroll
            for (int p = 0; p < 4; p++) {
                uint32_t bh[2][2], bl[2][2];
                ldsm4(bh[0][0], bh[0][1], bh[1][0], bh[1][1],
                      sKh32 + (uint32_t)(p*16)*(AP*2u) + kb + koff);
                ldsm4(bl[0][0], bl[0][1], bl[1][0], bl[1][1],
                      sKl32 + (uint32_t)(p*16)*(AP*2u) + kb + koff);
#pragma unroll
                for (int e = 0; e < 2; e++) {
                    mma_bf16(s[2*p + e], ah, bh[e]);
                    mma_bf16(s[2*p + e], ah, bl[e]);
                    mma_bf16(s[2*p + e], al, bh[e]);
                }
            }
        }

        if (kt == qt) {
            const int r0 = wid*16 + g, r1 = r0 + 8;
#pragma unroll
            for (int nb = 0; nb < 8; nb++) {
                int c0 = nb*8 + 2*t, c1 = c0 + 1;
                if (c0 > r0) s[nb][0] = -1e30f;
                if (c1 > r0) s[nb][1] = -1e30f;
                if (c0 > r1) s[nb][2] = -1e30f;
                if (c1 > r1) s[nb][3] = -1e30f;
            }
        }

        float mx0 = -1e30f, mx1 = -1e30f;
#pragma unroll
        for (int nb = 0; nb < 8; nb++) {
            mx0 = fmaxf(mx0, fmaxf(s[nb][0], s[nb][1]));
            mx1 = fmaxf(mx1, fmaxf(s[nb][2], s[nb][3]));
        }
        mx0 *= SC2; mx1 *= SC2;
#pragma unroll
        for (int off = 1; off <= 2; off <<= 1) {
            mx0 = fmaxf(mx0, __shfl_xor_sync(0xffffffffu, mx0, off));
            mx1 = fmaxf(mx1, __shfl_xor_sync(0xffffffffu, mx1, off));
        }
        float mn0 = fmaxf(m2[0], mx0), mn1 = fmaxf(m2[1], mx1);
        float corr0 = exp2f(m2[0] - mn0), corr1 = exp2f(m2[1] - mn1);
        float sum0 = 0.f, sum1 = 0.f;
#pragma unroll
        for (int nb = 0; nb < 8; nb++) {
            s[nb][0] = exp2f(s[nb][0]*SC2 - mn0);
            s[nb][1] = exp2f(s[nb][1]*SC2 - mn0);
            s[nb][2] = exp2f(s[nb][2]*SC2 - mn1);
            s[nb][3] = exp2f(s[nb][3]*SC2 - mn1);
            sum0 += s[nb][0] + s[nb][1];
            sum1 += s[nb][2] + s[nb][3];
        }
#pragma unroll
        for (int off = 1; off <= 2; off <<= 1) {
            sum0 += __shfl_xor_sync(0xffffffffu, sum0, off);
            sum1 += __shfl_xor_sync(0xffffffffu, sum1, off);
        }
        lsum[0] = lsum[0]*corr0 + sum0;
        lsum[1] = lsum[1]*corr1 + sum1;
        m2[0] = mn0; m2[1] = mn1;
#pragma unroll
        for (int nb = 0; nb < 16; nb++) {
            accO[nb][0] *= corr0; accO[nb][1] *= corr0;
            accO[nb][2] *= corr1; accO[nb][3] *= corr1;
        }

        uint32_t pah[4][4], pal[4][4];
#pragma unroll
        for (int kc = 0; kc < 4; kc++) {
            pah[kc][0] = pack_split(s[2*kc][0],   s[2*kc][1],   pal[kc][0]);
            pah[kc][1] = pack_split(s[2*kc][2],   s[2*kc][3],   pal[kc][1]);
            pah[kc][2] = pack_split(s[2*kc+1][0], s[2*kc+1][1], pal[kc][2]);
            pah[kc][3] = pack_split(s[2*kc+1][2], s[2*kc+1][3], pal[kc][3]);
        }

#pragma unroll
        for (int kc = 0; kc < 4; kc++) {
            const uint32_t kb = kc*32;
#pragma unroll
            for (int p = 0; p < 8; p++) {
                uint32_t vh[2][2], vl[2][2];
                ldsm4(vh[0][0], vh[0][1], vh[1][0], vh[1][1],
                      sVh32 + (uint32_t)(p*16)*(VP*2u) + kb + voff);
                ldsm4(vl[0][0], vl[0][1], vl[1][0], vl[1][1],
                      sVl32 + (uint32_t)(p*16)*(VP*2u) + kb + voff);
#pragma unroll
                for (int e = 0; e < 2; e++) {
                    mma_bf16(accO[2*p + e], pah[kc], vh[e]);
                    mma_bf16(accO[2*p + e], pah[kc], vl[e]);
                    mma_bf16(accO[2*p + e], pal[kc], vh[e]);
                }
            }
        }
        __syncthreads();
    }

    const float inv0 = 1.f / lsum[0], inv1 = 1.f / lsum[1];
    const long obase = ((long)(b*SEQ + q0 + wid*16))*DMODEL + h*HDIM;
#pragma unroll
    for (int nb = 0; nb < 16; nb++) {
        int col = nb*8 + 2*t;
        uint32_t c0, c1;
        uint32_t h0 = pack_f16pair(accO[nb][0]*inv0, accO[nb][1]*inv0, c0);
        uint32_t h1 = pack_f16pair(accO[nb][2]*inv1, accO[nb][3]*inv1, c1);
        *(uint32_t*)(Ch + obase + (long)g*DMODEL + col)     = h0;
        *(uint32_t*)(Cc + obase + (long)g*DMODEL + col)     = c0;
        *(uint32_t*)(Ch + obase + (long)(g+8)*DMODEL + col) = h1;
        *(uint32_t*)(Cc + obase + (long)(g+8)*DMODEL + col) = c1;
    }
}

// ---------------------------------------------------------------------------
// Host launcher
// ---------------------------------------------------------------------------
extern "C" void kernel_launch(void* const* d_in, const int* in_sizes, int n_in,
                              void* d_out, int out_size)
{
    const float* x  = (const float*)d_in[0];
    const float* wq = (const float*)d_in[1];
    const float* wk = (const float*)d_in[2];
    const float* wv = (const float*)d_in[3];
    const float* wo = (const float*)d_in[4];
    const float* bo = (const float*)d_in[5];
    float* out = (float*)d_out;

    __half *x16h, *x16c, *wq16h, *wq16c, *wk16h, *wk16c, *wv16h, *wv16c, *wo16h, *wo16c;
    __half *c16h, *c16c;
    __nv_bfloat16 *qh, *ql, *kh, *kl, *vh, *vl, *vth, *vtl;
    cudaGetSymbolAddress((void**)&x16h, g_x16h);   cudaGetSymbolAddress((void**)&x16c, g_x16c);
    cudaGetSymbolAddress((void**)&wq16h, g_wq16h); cudaGetSymbolAddress((void**)&wq16c, g_wq16c);
    cudaGetSymbolAddress((void**)&wk16h, g_wk16h); cudaGetSymbolAddress((void**)&wk16c, g_wk16c);
    cudaGetSymbolAddress((void**)&wv16h, g_wv16h); cudaGetSymbolAddress((void**)&wv16c, g_wv16c);
    cudaGetSymbolAddress((void**)&wo16h, g_wo16h); cudaGetSymbolAddress((void**)&wo16c, g_wo16c);
    cudaGetSymbolAddress((void**)&qh, g_q_h);      cudaGetSymbolAddress((void**)&ql, g_q_l);
    cudaGetSymbolAddress((void**)&kh, g_k_h);      cudaGetSymbolAddress((void**)&kl, g_k_l);
    cudaGetSymbolAddress((void**)&vh, g_v_h);      cudaGetSymbolAddress((void**)&vl, g_v_l);
    cudaGetSymbolAddress((void**)&vth, g_vt_h);    cudaGetSymbolAddress((void**)&vtl, g_vt_l);
    cudaGetSymbolAddress((void**)&c16h, g_c16h);   cudaGetSymbolAddress((void**)&c16c, g_c16c);

    static bool configured = false;
    if (!configured) {
        cudaFuncSetAttribute(gemm6<true>,  cudaFuncAttributeMaxDynamicSharedMemorySize, GEMM_SMEM);
        cudaFuncSetAttribute(gemm6<false>, cudaFuncAttributeMaxDynamicSharedMemorySize, GEMM_SMEM);
        cudaFuncSetAttribute(attn_mma, cudaFuncAttributeMaxDynamicSharedMemorySize, ATTN_SMEM);
        configured = true;
    }

    // 1) fp16 Karatsuba splits: x + fused 4-weight
    split16_kernel<<<(NTOK/4 + 255)/256, 256>>>((const float4*)x, (uint2*)x16h, (uint2*)x16c, NTOK/4);
    {
        SplitW w = {};
        w.s0 = (const float4*)wq; w.s1 = (const float4*)wk;
        w.s2 = (const float4*)wv; w.s3 = (const float4*)wo;
        w.h0 = (uint2*)wq16h; w.h1 = (uint2*)wk16h; w.h2 = (uint2*)wv16h; w.h3 = (uint2*)wo16h;
        w.c0 = (uint2*)wq16c; w.c1 = (uint2*)wk16c; w.c2 = (uint2*)wv16c; w.c3 = (uint2*)wo16c;
        split16x4_kernel<<<dim3((NW/4 + 255)/256, 1, 4), 256>>>(w, NW/4);
    }

    // 2) fused QKV projection: grid (32 m-blocks fast, 48 = 3 outputs x 16 n-blocks)
    {
        GemmArgs a = {};
        a.Ah = x16h; a.Ac = x16c;
        a.Bh0 = wq16h; a.Bc0 = wq16c; a.Bh1 = wk16h; a.Bc1 = wk16c; a.Bh2 = wv16h; a.Bc2 = wv16c;
        a.Ch0 = qh;  a.Cl0 = ql;  a.Ch1 = kh;  a.Cl1 = kl;  a.Ch2 = vh;  a.Cl2 = vl;
        gemm6<true><<<dim3(MTOT/128, 48), 512, GEMM_SMEM>>>(a);
    }

    // 3) V transpose, hi and lo fused
    transpose_bf16<<<dim3(64, 64, 2*BATCH), 256>>>(vh, vth, vl, vtl);

    // 4) attention (bf16x3), emits ctx as fp16 Karatsuba pair
    attn_mma<<<dim3(SEQ/64, NHEAD, BATCH), 128, ATTN_SMEM>>>(qh, ql, kh, kl, vth, vtl, c16h, c16c);

    // 5) output projection (fp16 Karatsuba, fp32 + bias out)
    {
        GemmArgs a = {};
        a.Ah = c16h; a.Ac = c16c;
        a.Bh0 = wo16h; a.Bc0 = wo16c; a.Bh1 = wo16h; a.Bc1 = wo16c; a.Bh2 = wo16h; a.Bc2 = wo16c;
        a.Cf = out; a.bias = bo;
        gemm6<false><<<dim3(MTOT/128, 16), 512, GEMM_SMEM>>>(a);
    }
}